// round 2
// baseline (speedup 1.0000x reference)
#include <cuda_runtime.h>

// FIR: out[b,t] = sum_{i=0..KT-1} krev[i] * u[b, t+i],  krev[i] = kernel[KT-1-i]
// B=1000, T_OUT=20000, T_IN=20180+KT? (T_OUT + KT - 1 = 20180), KT=181.

#define KT       181
#define OPT      8                  // outputs per thread
#define NTHREADS 256
#define TILE_T   (NTHREADS * OPT)   // 2048 outputs per block
#define KPAD     192                // padded tap count (multiple of 8)
#define SU_LEN   (TILE_T + KPAD)    // 2240 floats staged per block

__global__ __launch_bounds__(NTHREADS)
void fir_sliding_kernel(const float* __restrict__ u,
                        const float* __restrict__ kern,
                        float* __restrict__ out,
                        int t_out, int t_in)
{
    __shared__ __align__(16) float s_u[SU_LEN];
    __shared__ float s_k[KPAD];

    const int row = blockIdx.y;
    const int t0  = blockIdx.x * TILE_T;
    const int tid = threadIdx.x;

    const float* __restrict__ urow = u + (long long)row * t_in;

    // Stage reversed, zero-padded kernel taps.
    for (int i = tid; i < KPAD; i += NTHREADS)
        s_k[i] = (i < KT) ? kern[KT - 1 - i] : 0.0f;

    // Stage input tile (coalesced scalar loads), zero-fill out-of-range.
    for (int i = tid; i < SU_LEN; i += NTHREADS) {
        int g = t0 + i;
        s_u[i] = (g < t_in) ? urow[g] : 0.0f;
    }
    __syncthreads();

    const int t_local = tid * OPT;           // multiple of 8 -> 32B aligned in s_u
    const int t       = t0 + t_local;
    if (t >= t_out) return;                  // no further barriers below

    float acc[OPT];
    #pragma unroll
    for (int c = 0; c < OPT; c++) acc[c] = 0.0f;

    // Sliding window of 16 input values in registers.
    float r[16];
    {
        const float4* p = reinterpret_cast<const float4*>(s_u + t_local);
        float4 a = p[0], b = p[1];
        r[0]=a.x; r[1]=a.y; r[2]=a.z; r[3]=a.w;
        r[4]=b.x; r[5]=b.y; r[6]=b.z; r[7]=b.w;
    }

    // Main loop: 22 blocks of 8 taps (taps 0..175).
    #pragma unroll 2
    for (int ib = 0; ib < 22; ib++) {
        const int i = ib * 8;
        // Load next 8 window values (16B-aligned LDS.128).
        {
            const float4* p = reinterpret_cast<const float4*>(s_u + t_local + i + 8);
            float4 a = p[0], b = p[1];
            r[8]=a.x; r[9]=a.y; r[10]=a.z; r[11]=a.w;
            r[12]=b.x; r[13]=b.y; r[14]=b.z; r[15]=b.w;
        }
        #pragma unroll
        for (int j = 0; j < 8; j++) {
            const float kj = s_k[i + j];
            #pragma unroll
            for (int c = 0; c < OPT; c++)
                acc[c] = fmaf(kj, r[j + c], acc[c]);
        }
        #pragma unroll
        for (int c = 0; c < 8; c++) r[c] = r[8 + c];
    }

    // Tail taps 176..180 (5 taps). Window r[0..7] = u[t+176 .. t+183];
    // need up to u[t+187] -> load r[8..11].
    {
        const float4* p = reinterpret_cast<const float4*>(s_u + t_local + 184);
        float4 a = p[0];
        r[8]=a.x; r[9]=a.y; r[10]=a.z; r[11]=a.w;
    }
    #pragma unroll
    for (int j = 0; j < 5; j++) {
        const float kj = s_k[176 + j];
        #pragma unroll
        for (int c = 0; c < OPT; c++)
            acc[c] = fmaf(kj, r[j + c], acc[c]);
    }

    float* __restrict__ orow = out + (long long)row * t_out + t;
    if ((t_out & 3) == 0) {
        // t multiple of 8, rows 4-float aligned -> 16B-aligned stores.
        reinterpret_cast<float4*>(orow)[0] = make_float4(acc[0], acc[1], acc[2], acc[3]);
        reinterpret_cast<float4*>(orow)[1] = make_float4(acc[4], acc[5], acc[6], acc[7]);
    } else {
        #pragma unroll
        for (int c = 0; c < OPT; c++) orow[c] = acc[c];
    }
}

// Generic fallback for unexpected tap counts (defensive; not the hot path).
__global__ void fir_generic_kernel(const float* __restrict__ u,
                                   const float* __restrict__ kern,
                                   float* __restrict__ out,
                                   int t_out, int t_in, int kt)
{
    long long idx = (long long)blockIdx.x * blockDim.x + threadIdx.x;
    long long total = (long long)gridDim.y * t_out;
    int row = blockIdx.y;
    int t = (int)idx;
    if (t >= t_out) return;
    const float* urow = u + (long long)row * t_in;
    float acc = 0.0f;
    for (int i = 0; i < kt; i++)
        acc = fmaf(kern[kt - 1 - i], urow[t + i], acc);
    out[(long long)row * t_out + t] = acc;
    (void)total;
}

extern "C" void kernel_launch(void* const* d_in, const int* in_sizes, int n_in,
                              void* d_out, int out_size)
{
    const float* u    = (const float*)d_in[0];
    const float* kern = (const float*)d_in[1];
    float* out        = (float*)d_out;

    const int kt = in_sizes[1];
    // in_sizes[0] = B*(T_OUT + kt - 1), out_size = B*T_OUT
    const int b_total = (in_sizes[0] - out_size) / (kt - 1);
    const int t_out   = out_size / b_total;
    const int t_in    = in_sizes[0] / b_total;

    if (kt == KT) {
        dim3 grid((t_out + TILE_T - 1) / TILE_T, b_total);
        fir_sliding_kernel<<<grid, NTHREADS>>>(u, kern, out, t_out, t_in);
    } else {
        dim3 grid((t_out + 255) / 256, b_total);
        fir_generic_kernel<<<grid, 256>>>(u, kern, out, t_out, t_in, kt);
    }
}